// round 15
// baseline (speedup 1.0000x reference)
// LocallyConnected2d forward (B=16, C=32, O=32, HW=64x64, 3x3, pad=1), sm_100a.
// Block = 8 adjacent output pixels, 128 threads; warp = 2 pixels (16 lanes
// each); thread tile 4b x 8o, fp32x2 packed over channel pairs.
// Weight smem layout per c-pair: row pk = pix*9+k holds 64 floats; 16B chunk
// j of o-slot og sits at granule (4j+og+rot(pk)) mod 16,
// rot(pk) = (F0(pk%9)+4*(pk/9)) mod 8, F0={0,1,2,3,4,5,6,7,3}; floats in a
// granule rotate by 2*((pk/9)&1). Compute LDS.128 = 1 wavefront (broadcast);
// staging = cc-paired STS.64, <=2-way. Readers undo rotation via oi^(pix&1).
// R15: x tile fully smem-resident staged with an MLP-friendly prologue
// (32 outstanding LDGs per batch), steady loop stages weights only with
// distance-2 register prefetch + distance-4 L2 prefetch.

#include <cuda_runtime.h>

typedef unsigned long long uu64;

__device__ __forceinline__ uu64 packed_fma(uu64 a, uu64 b, uu64 c) {
    uu64 d;
    asm("fma.rn.f32x2 %0, %1, %2, %3;" : "=l"(d) : "l"(a), "l"(b), "l"(c));
    return d;
}

#define WB_F 4608
#define XT_F 1080
#define XR_BASE (2 * WB_F)
#define TOTAL_F (2 * WB_F + 16 * XT_F)     // 26496 floats = 103.5 KB
#define CSTRIDE 36864

// smem float offset of weight element (pk, o, cc)
__device__ __forceinline__ int woffset(int pk, int o, int cc) {
    int g16  = (o & 7) * 2 + cc;
    int base = (g16 & ~3) + (o >> 3);
    int pos  = g16 & 3;
    int p  = (pk * 57) >> 9;               // pk / 9 for pk < 72
    int q  = pk - p * 9;
    int f0 = q - 5 * (q >> 3);             // {0,1,2,3,4,5,6,7,3}
    int rt = (f0 + 4 * p) & 7;
    return pk * 64 + ((base + rt) & 15) * 4 + ((pos + 2 * (p & 1)) & 3);
}

__global__ __launch_bounds__(128, 2)
void lc2d_fwd(const float* __restrict__ xin,
              const float* __restrict__ wgt,
              float* __restrict__ out)
{
    extern __shared__ __align__(16) float sm[];

    const int tid  = threadIdx.x;
    const int lane = tid & 31;
    const int og   = lane & 3;
    const int bg   = (lane >> 2) & 3;
    const int pix  = (tid >> 5) * 2 + (lane >> 4);
    const int swp  = pix & 1;

    const int oh      = blockIdx.y;
    const int ow0     = blockIdx.x << 3;
    const int pixbase = oh * 64 + ow0;

    // ---- w staging invariants: 4 cc-pair float4 items + 1 leftover ----
    int wbase4[4];
    unsigned woff64[8];
#pragma unroll
    for (int j = 0; j < 4; ++j) {
        int idx = j * 128 + tid;
        int o   = idx >> 4;
        int v4  = idx & 15;
        wbase4[j] = o * (32 * CSTRIDE) + pixbase * 9 + v4 * 4;
        unsigned a = 0, b = 0;
#pragma unroll
        for (int e = 0; e < 4; ++e) {
            int off = woffset(v4 * 4 + e, o, 0);     // cc=1 at off+1
            if (e < 2) a |= (unsigned)off << (16 * e);
            else       b |= (unsigned)off << (16 * (e - 2));
        }
        woff64[j * 2] = a; woff64[j * 2 + 1] = b;
    }
    int wlbase;
    unsigned wloff[2];
    {
        int o  = tid >> 2;
        int t2 = tid & 3;
        int cc = t2 & 1;
        int v4 = 16 + (t2 >> 1);
        wlbase = (o * 32 + cc) * CSTRIDE + pixbase * 9 + v4 * 4;
        unsigned a = 0, b = 0;
#pragma unroll
        for (int e = 0; e < 4; ++e) {
            int off = woffset(v4 * 4 + e, o, cc);
            if (e < 2) a |= (unsigned)off << (16 * e);
            else       b |= (unsigned)off << (16 * (e - 2));
        }
        wloff[0] = a; wloff[1] = b;
    }

    const int wread = pix * 576;
    const int xread = pix * 36 + bg * 8;

    uu64 acc[4][8];
#pragma unroll
    for (int i = 0; i < 4; ++i)
#pragma unroll
        for (int j = 0; j < 8; ++j) acc[i][j] = 0ull;

    float4 wA[4], wB[4], wL;

#define W_LOADS(CC2)                                                          \
    do {                                                                      \
        int cl = (CC2) * (2 * CSTRIDE);                                       \
        _Pragma("unroll")                                                     \
        for (int j = 0; j < 4; ++j) {                                         \
            wA[j] = *reinterpret_cast<const float4*>(wgt + wbase4[j] + cl);   \
            wB[j] = *reinterpret_cast<const float4*>(wgt + wbase4[j] + cl     \
                                                     + CSTRIDE);              \
        }                                                                     \
        wL = *reinterpret_cast<const float4*>(wgt + wlbase + cl);             \
    } while (0)

#define W_STAGE(BUF)                                                          \
    do {                                                                      \
        float* wd = sm + (BUF) * WB_F;                                        \
        _Pragma("unroll")                                                     \
        for (int j = 0; j < 4; ++j) {                                         \
            const float* a = reinterpret_cast<const float*>(&wA[j]);          \
            const float* b = reinterpret_cast<const float*>(&wB[j]);          \
            _Pragma("unroll")                                                 \
            for (int e = 0; e < 4; ++e) {                                     \
                unsigned off = (woff64[j*2 + (e>>1)] >> (16*(e&1))) & 0xffffu;\
                *reinterpret_cast<float2*>(wd + off) =                        \
                    make_float2(a[e], b[e]);                                  \
            }                                                                 \
        }                                                                     \
        {                                                                     \
            const float* l = reinterpret_cast<const float*>(&wL);             \
            wd[wloff[0] & 0xffffu] = l[0];                                    \
            wd[wloff[0] >> 16]     = l[1];                                    \
            wd[wloff[1] & 0xffffu] = l[2];                                    \
            wd[wloff[1] >> 16]     = l[3];                                    \
        }                                                                     \
    } while (0)

#define W_PF(CC2)                                                             \
    do {                                                                      \
        int cl = (CC2) * (2 * CSTRIDE);                                       \
        _Pragma("unroll")                                                     \
        for (int j = 0; j < 4; ++j) {                                         \
            asm volatile("prefetch.global.L2 [%0];" ::                        \
                         "l"(wgt + wbase4[j] + cl));                          \
            asm volatile("prefetch.global.L2 [%0];" ::                        \
                         "l"(wgt + wbase4[j] + cl + CSTRIDE));                \
        }                                                                     \
        asm volatile("prefetch.global.L2 [%0];" :: "l"(wgt + wlbase + cl));   \
    } while (0)

    // prologue A: kick off weight loads for c-pair 0; warm L2 ahead
    W_LOADS(0);
    W_PF(1);

    // prologue B: stage the whole x tile with high MLP (s-pairs, 32 LDGs out)
    {
        int xg[8], xo[8];
#pragma unroll
        for (int s = 0; s < 8; ++s) {
            int i = tid + s * 128;
            xg[s] = -1; xo[s] = -1;
            if (i < 960) {
                int col = i % 10;
                int r   = i / 10;
                int row = r % 3;
                int qb  = r / 3;
                int b   = qb >> 1;
                int cc  = qb & 1;
                xo[s] = (row * 10 + col) * 36 + b * 2 + cc;
                int ih = oh - 1 + row;
                int iw = ow0 - 1 + col;
                if ((unsigned)ih < 64u && (unsigned)iw < 64u)
                    xg[s] = (b * 32 + cc) * 4096 + ih * 64 + iw;
            }
        }
#pragma unroll
        for (int sp = 0; sp < 8; sp += 2) {
            float v0[16], v1[16];
#pragma unroll
            for (int c2 = 0; c2 < 16; ++c2) {
                v0[c2] = (xg[sp]     >= 0) ? __ldg(xin + xg[sp]     + c2*8192) : 0.f;
                v1[c2] = (xg[sp + 1] >= 0) ? __ldg(xin + xg[sp + 1] + c2*8192) : 0.f;
            }
#pragma unroll
            for (int c2 = 0; c2 < 16; ++c2) {
                if (xo[sp]     >= 0) sm[XR_BASE + c2*XT_F + xo[sp]]     = v0[c2];
                if (xo[sp + 1] >= 0) sm[XR_BASE + c2*XT_F + xo[sp + 1]] = v1[c2];
            }
        }
    }

    // prologue C: stage w buf0, prefetch c-pair 1, warm L2 further
    W_STAGE(0);
    W_LOADS(1);
    W_PF(2);
    W_PF(3);

    // steady state: weight-only pipeline; x read in place
    for (int cc2 = 0; cc2 < 16; ++cc2) {
        const int buf = cc2 & 1;
        __syncthreads();                    // w buf staged; buf^1 consumed
        if (cc2 < 15) W_STAGE(buf ^ 1);
        if (cc2 < 14) W_LOADS(cc2 + 2);
        if (cc2 < 12) W_PF(cc2 + 4);

        const float* wp = sm + buf * WB_F + wread;
        const float* xp = sm + XR_BASE + cc2 * XT_F + xread;
#pragma unroll
        for (int k = 0; k < 9; ++k) {
            const int f0k = (k < 8) ? k : 3;
            const float* xb = xp + ((k / 3) * 10 + (k % 3)) * 36;
            ulonglong2 xlo = *reinterpret_cast<const ulonglong2*>(xb);
            ulonglong2 xhi = *reinterpret_cast<const ulonglong2*>(xb + 4);
            uu64 xv[4] = {xlo.x, xlo.y, xhi.x, xhi.y};

            const float* wkb = wp + k * 64;
            const int t = og + ((f0k + 4 * pix) & 7);
            {   // oi 0..3
                ulonglong2 wa = *reinterpret_cast<const ulonglong2*>(wkb + ((t    ) & 15) * 4);
                ulonglong2 wc = *reinterpret_cast<const ulonglong2*>(wkb + ((t + 4) & 15) * 4);
                uu64 wv[4] = {wa.x, wa.y, wc.x, wc.y};
#pragma unroll
                for (int bi = 0; bi < 4; ++bi)
#pragma unroll
                    for (int oi = 0; oi < 4; ++oi)
                        acc[bi][oi] = packed_fma(xv[bi], wv[oi], acc[bi][oi]);
            }
            {   // oi 4..7
                ulonglong2 wa = *reinterpret_cast<const ulonglong2*>(wkb + ((t +  8) & 15) * 4);
                ulonglong2 wc = *reinterpret_cast<const ulonglong2*>(wkb + ((t + 12) & 15) * 4);
                uu64 wv[4] = {wa.x, wa.y, wc.x, wc.y};
#pragma unroll
                for (int bi = 0; bi < 4; ++bi)
#pragma unroll
                    for (int oi = 0; oi < 4; ++oi)
                        acc[bi][oi + 4] = packed_fma(xv[bi], wv[oi], acc[bi][oi + 4]);
            }
        }
    }

    // epilogue: cc-pair reduce, rotation-swap undo, smem transpose, 32B STG
    __syncthreads();
#pragma unroll
    for (int bi = 0; bi < 4; ++bi)
#pragma unroll
        for (int oi = 0; oi < 8; ++oi) {
            union { uu64 u; float2 f; } cv;
            cv.u = acc[bi][oi];
            int bo = (bg * 4 + bi) * 32 + og * 8 + (oi ^ swp);
            sm[bo * 10 + pix] = cv.f.x + cv.f.y;
        }
    __syncthreads();
#pragma unroll
    for (int rr = 0; rr < 4; ++rr) {
        int r = tid + rr * 128;             // r = b*32 + o
        const float* sp = sm + r * 10;
        float4 lo = make_float4(sp[0], sp[1], sp[2], sp[3]);
        float4 hi = make_float4(sp[4], sp[5], sp[6], sp[7]);
        float* op = out + (size_t)r * 4096 + pixbase;
        *reinterpret_cast<float4*>(op)     = lo;
        *reinterpret_cast<float4*>(op + 4) = hi;
    }
#undef W_LOADS
#undef W_STAGE
#undef W_PF
}

extern "C" void kernel_launch(void* const* d_in, const int* in_sizes, int n_in,
                              void* d_out, int out_size) {
    const float* x = (const float*)d_in[0];   // [16,32,64,64] float32
    const float* w = (const float*)d_in[1];   // [32,32,64,64,9] float32
    float* y = (float*)d_out;                 // [16,32,64,64] float32
    cudaFuncSetAttribute(lc2d_fwd,
                         cudaFuncAttributeMaxDynamicSharedMemorySize,
                         TOTAL_F * 4);
    dim3 grid(8, 64);
    lc2d_fwd<<<grid, 128, TOTAL_F * 4>>>(x, w, y);
}

// round 17
// speedup vs baseline: 1.3147x; 1.3147x over previous
// LocallyConnected2d forward: B=16, C=32, O=32, spatial 64x64, 3x3, pad 1.
// sm_100a. Eight-warp blocks (256 threads); each warp owns ONE output pixel
// and performs the full 16-batch x 32-channel per-pixel GEMM over K=32c*9k.
// Lane split: og = lane&7 (4 out-channels), bg = lane>>3 (4 batches);
// per-thread accumulator 4b x 4o in fp32x2 (even channel .lo, odd .hi).
//
// Weight shared layout: row pk (= pixel*9 + k) spans 64 floats (16 granules
// of 16 bytes). For o-group og, the cc-paired quad of o = 4*og + {0,1} sits
// at granule (og + rot) mod 16 and o = 4*og + {2,3} at (og + 8 + rot) mod 16,
// rot = (pk >> 2) & 7. Reader LDS.128s touch 8 consecutive granules ->
// distinct mod 8 -> conflict-free. Staging uses cc-paired STS.64.
// x shared layout: pos*36 + b*2 + cc; reads broadcast across og lanes.
// Two-deep register prefetch of the next c-pairs, double-buffered smem,
// one __syncthreads per iteration. Static shared memory 45.5 KB.

#include <cuda_runtime.h>

typedef unsigned long long ullv;

__device__ __forceinline__ ullv fmaf32x2(ullv a, ullv b, ullv c) {
    ullv d;
    asm("fma.rn.f32x2 %0, %1, %2, %3;" : "=l"(d) : "l"(a), "l"(b), "l"(c));
    return d;
}

#define WREG_F 4608
#define XREG_F 1080
#define XSTART (2 * WREG_F)

__global__ __launch_bounds__(256, 2)
void lc2d_run(const float* __restrict__ xin,
              const float* __restrict__ wgt,
              float* __restrict__ out)
{
    __shared__ __align__(16) float shm[2 * WREG_F + 2 * XREG_F];  // 11376

    const int tid  = threadIdx.x;
    const int lane = tid & 31;
    const int pixw = tid >> 5;          // warp index = pixel 0..7
    const int og   = lane & 7;
    const int bg   = lane >> 3;

    const int oh      = blockIdx.y;
    const int ow0     = blockIdx.x << 3;
    const int pixbase = oh * 64 + ow0;

    // weight staging: 576 (o, v4) cc-pair items; slots 0,1 for everyone,
    // slot 2 only for tid < 64
    int wgof[3], wsof[3];
#pragma unroll
    for (int j = 0; j < 3; ++j) {
        int p  = (j < 2) ? j * 256 + tid : 512 + (tid & 63);
        int o  = p / 18;
        int v4 = p - o * 18;
        wgof[j] = o * 1179648 + pixbase * 9 + v4 * 4;   // o*(32*36864)
        int oi  = o & 3;
        int ogs = o >> 2;
        int grn = (ogs + 8 * (oi >> 1) + (v4 & 7)) & 15;
        wsof[j] = v4 * 256 + grn * 4 + (oi & 1) * 2;    // + e*64 per element
    }
    const bool slot2 = (tid < 64);

    // x staging: 960 items; slots 0..2 for everyone, slot 3 for tid < 192
    int xgof[4], xsof[4];
#pragma unroll
    for (int s = 0; s < 4; ++s) {
        int i = tid + s * 256;
        xgof[s] = -1; xsof[s] = -1;
        if (i < 960) {
            int col = i % 10, r = i / 10;
            int row = r % 3, qb = r / 3;
            int b = qb >> 1, cc = qb & 1;
            xsof[s] = (row * 10 + col) * 36 + b * 2 + cc;
            int ih = oh - 1 + row, iw = ow0 - 1 + col;
            if ((unsigned)ih < 64u && (unsigned)iw < 64u)
                xgof[s] = (b * 32 + cc) * 4096 + ih * 64 + iw;
        }
    }

    const int pk0   = 9 * pixw;
    const int wrdof = pixw * 576;
    const int xrdof = pixw * 36 + bg * 8;

    ullv acc[4][4];
#pragma unroll
    for (int i = 0; i < 4; ++i)
#pragma unroll
        for (int j = 0; j < 4; ++j) acc[i][j] = 0ull;

    float4 wqa[3], wqb[3];
    float  xq[4];

#define LD_NEXT(CC2)                                                          \
    do {                                                                      \
        int cl = (CC2) * 73728;                                               \
        _Pragma("unroll")                                                     \
        for (int j = 0; j < 2; ++j) {                                         \
            wqa[j] = *reinterpret_cast<const float4*>(wgt + wgof[j] + cl);    \
            wqb[j] = *reinterpret_cast<const float4*>(wgt + wgof[j] + cl      \
                                                      + 36864);               \
        }                                                                     \
        if (slot2) {                                                          \
            wqa[2] = *reinterpret_cast<const float4*>(wgt + wgof[2] + cl);    \
            wqb[2] = *reinterpret_cast<const float4*>(wgt + wgof[2] + cl      \
                                                      + 36864);               \
        }                                                                     \
        int cx = (CC2) * 8192;                                                \
        _Pragma("unroll")                                                     \
        for (int s = 0; s < 4; ++s)                                           \
            if (xsof[s] >= 0)                                                 \
                xq[s] = (xgof[s] >= 0) ? __ldg(xin + xgof[s] + cx) : 0.f;     \
    } while (0)

#define ST_BUF(BUF)                                                           \
    do {                                                                      \
        float* wd = shm + (BUF) * WREG_F;                                     \
        _Pragma("unroll")                                                     \
        for (int j = 0; j < 2; ++j) {                                         \
            const float* a = reinterpret_cast<const float*>(&wqa[j]);         \
            const float* b = reinterpret_cast<const float*>(&wqb[j]);         \
            _Pragma("unroll")                                                 \
            for (int e = 0; e < 4; ++e)                                       \
                *reinterpret_cast<float2*>(wd + wsof[j] + e * 64) =           \
                    make_float2(a[e], b[e]);                                  \
        }                                                                     \
        if (slot2) {                                                          \
            const float* a = reinterpret_cast<const float*>(&wqa[2]);         \
            const float* b = reinterpret_cast<const float*>(&wqb[2]);         \
            _Pragma("unroll")                                                 \
            for (int e = 0; e < 4; ++e)                                       \
                *reinterpret_cast<float2*>(wd + wsof[2] + e * 64) =           \
                    make_float2(a[e], b[e]);                                  \
        }                                                                     \
        float* xd = shm + XSTART + (BUF) * XREG_F;                            \
        _Pragma("unroll")                                                     \
        for (int s = 0; s < 4; ++s)                                           \
            if (xsof[s] >= 0) xd[xsof[s]] = xq[s];                            \
    } while (0)

    LD_NEXT(0);
    ST_BUF(0);
    LD_NEXT(1);

    for (int cc2 = 0; cc2 < 16; ++cc2) {
        const int buf = cc2 & 1;
        __syncthreads();                    // buf ready; buf^1 drained
        if (cc2 < 15) ST_BUF(buf ^ 1);
        if (cc2 < 14) LD_NEXT(cc2 + 2);

        const float* wp = shm + buf * WREG_F + wrdof;
        const float* xp = shm + XSTART + buf * XREG_F + xrdof;
#pragma unroll
        for (int k = 0; k < 9; ++k) {
            const float* xb = xp + ((k / 3) * 10 + (k % 3)) * 36;
            ulonglong2 xlo = *reinterpret_cast<const ulonglong2*>(xb);
            ulonglong2 xhi = *reinterpret_cast<const ulonglong2*>(xb + 4);
            ullv xv[4] = {xlo.x, xlo.y, xhi.x, xhi.y};   // b = 4*bg+0..3

            const int rot = ((pk0 + k) >> 2) & 7;
            const float* wkb = wp + k * 64;
            ulonglong2 w01 = *reinterpret_cast<const ulonglong2*>(
                wkb + ((og + rot) & 15) * 4);            // o = 4*og+0,1
            ulonglong2 w23 = *reinterpret_cast<const ulonglong2*>(
                wkb + ((og + 8 + rot) & 15) * 4);        // o = 4*og+2,3
            ullv wv[4] = {w01.x, w01.y, w23.x, w23.y};
#pragma unroll
            for (int bi = 0; bi < 4; ++bi)
#pragma unroll
                for (int oi = 0; oi < 4; ++oi)
                    acc[bi][oi] = fmaf32x2(xv[bi], wv[oi], acc[bi][oi]);
        }
    }

    // epilogue: reduce cc pair, transpose through smem, 32-byte stores
    __syncthreads();
#pragma unroll
    for (int bi = 0; bi < 4; ++bi)
#pragma unroll
        for (int oi = 0; oi < 4; ++oi) {
            union { ullv u; float2 f; } cv;
            cv.u = acc[bi][oi];
            int bo = (bg * 4 + bi) * 32 + og * 4 + oi;   // b*32 + o
            shm[bo * 10 + pixw] = cv.f.x + cv.f.y;
        }
    __syncthreads();
#pragma unroll
    for (int rr = 0; rr < 2; ++rr) {
        int r = tid + rr * 256;             // r = b*32 + o
        const float* sp = shm + r * 10;
        float4 lo = make_float4(sp[0], sp[1], sp[2], sp[3]);
        float4 hi = make_float4(sp[4], sp[5], sp[6], sp[7]);
        float* op = out + (size_t)r * 4096 + pixbase;
        *reinterpret_cast<float4*>(op)     = lo;
        *reinterpret_cast<float4*>(op + 4) = hi;
    }
#undef LD_NEXT
#undef ST_BUF
}

extern "C" void kernel_launch(void* const* d_in, const int* in_sizes, int n_in,
                              void* d_out, int out_size) {
    const float* x = (const float*)d_in[0];   // [16,32,64,64] float32
    const float* w = (const float*)d_in[1];   // [32,32,64,64,9] float32
    float* y = (float*)d_out;                 // [16,32,64,64] float32
    dim3 grid(8, 64);
    lc2d_run<<<grid, 256>>>(x, w, y);
}